// round 12
// baseline (speedup 1.0000x reference)
#include <cuda_runtime.h>
#include <math.h>

#define Hs    64
#define SEQ   2048
#define Bt    256
#define IN    32
#define GATES 256   // 4*H

typedef unsigned long long u64;

__device__ float g_xproj[(size_t)SEQ * Bt * GATES];   // [t][row][g], bias0 folded

__device__ __forceinline__ u64 fma2(u64 a, u64 b, u64 c) {
    u64 d;
    asm("fma.rn.f32x2 %0, %1, %2, %3;" : "=l"(d) : "l"(a), "l"(b), "l"(c));
    return d;
}
__device__ __forceinline__ u64 pk(float a, float b) {
    u64 r;
    asm("mov.b64 %0, {%1, %2};" : "=l"(r) : "f"(a), "f"(b));
    return r;
}
__device__ __forceinline__ float hsum(u64 v) {
    float a, b;
    asm("mov.b64 {%0, %1}, %2;" : "=f"(a), "=f"(b) : "l"(v));
    return a + b;
}
__device__ __forceinline__ float ex2a(float x) {
    float y; asm("ex2.approx.f32 %0, %1;" : "=f"(y) : "f"(x)); return y;
}
__device__ __forceinline__ float rcpa(float x) {
    float y; asm("rcp.approx.f32 %0, %1;" : "=f"(y) : "f"(x)); return y;
}
__device__ __forceinline__ float sigf(float x) {
    return rcpa(1.0f + ex2a(-1.4426950408889634f * x));
}
__device__ __forceinline__ float tanha(float x) {
    float y; asm("tanh.approx.f32 %0, %1;" : "=f"(y) : "f"(x)); return y;
}
__device__ __forceinline__ void bar_arrive(int id) {
    asm volatile("bar.arrive %0, 512;" :: "r"(id) : "memory");
}
__device__ __forceinline__ void bar_wait(int id) {
    asm volatile("bar.sync %0, 512;" :: "r"(id) : "memory");
}

// ============================================================================
// Prepass (round-4 proven, ~350us): xproj = Wih0·x + bih0 + bhh0
// ============================================================================
__global__ void __launch_bounds__(256)
xproj_kernel(const float* __restrict__ x,
             const float* __restrict__ Wih0,
             const float* __restrict__ bih0,
             const float* __restrict__ bhh0)
{
    __shared__ float sx[64 * IN];
    const int g   = threadIdx.x;
    const int row = blockIdx.y;
    const int t0  = blockIdx.x * 64;

    const float* xs = x + ((size_t)row * SEQ + t0) * IN;
    for (int i = g; i < 64 * IN / 4; i += 256)
        ((float4*)sx)[i] = ((const float4*)xs)[i];

    u64 w[IN / 2];
    const u64* wp = (const u64*)(Wih0 + g * IN);
#pragma unroll
    for (int k = 0; k < IN / 2; k++) w[k] = wp[k];
    const u64 bp = pk(bih0[g] + bhh0[g], 0.0f);
    __syncthreads();

    for (int tt = 0; tt < 64; tt++) {
        const ulonglong2* xv = (const ulonglong2*)(sx + tt * IN);
        u64 a = bp;
#pragma unroll
        for (int k = 0; k < IN / 4; k++) {
            ulonglong2 v = xv[k];
            a = fma2(w[2 * k],     v.x, a);
            a = fma2(w[2 * k + 1], v.y, a);
        }
        g_xproj[((size_t)(t0 + tt) * Bt + row) * GATES + g] = hsum(a);
    }
}

// ============================================================================
// Main: r11 structure + split named barriers.
//   all: block1(H0) -> store a -> [non-L0u: arrive b1] -> block2(H1) -> store q
//   L0u: arrive b2, sync b1, update L0 (overlaps others' block2)
//   L1u: arrive b1 (early), sync b2, update L1 + head output
//   all: __syncthreads (b0) before next step
// ============================================================================
__global__ void __launch_bounds__(512, 1)
lstm2_r12(const float* __restrict__ h0g,
          const float* __restrict__ c0g,
          const float* __restrict__ Whh0,
          const float* __restrict__ Wih1,
          const float* __restrict__ Whh1,
          const float* __restrict__ bih1,
          const float* __restrict__ bhh1,
          const float* __restrict__ Wh,
          const float* __restrict__ bhp,
          float* __restrict__ out)
{
    __shared__ float sP[4 * 512];    // [layer*2+row][g*2+half]
    __shared__ float sH0[2 * Hs];    // [row][j]
    __shared__ float sH1[2 * Hs];
    __shared__ float sPr[8];         // [parity][4]

    const int tid  = threadIdx.x;
    const int g    = tid & 255;
    const int half = tid >> 8;
    const int r0   = blockIdx.x * 2;

    // register weights: half-rows (32 floats = 16 u64 each)
    u64 wh0[16], wx1[16], wh1[16];
    {
        const u64* p0 = (const u64*)(Whh0 + g * Hs + half * 32);
        const u64* p1 = (const u64*)(Wih1 + g * Hs + half * 32);
        const u64* p2 = (const u64*)(Whh1 + g * Hs + half * 32);
#pragma unroll
        for (int k = 0; k < 16; k++) { wh0[k] = p0[k]; wx1[k] = p1[k]; wh1[k] = p2[k]; }
    }
    const float b1  = bih1[g] + bhh1[g];
    const float bh0 = bhp[0];
    const float whj = Wh[tid & 63];

    const bool isL0u = (tid < 128);                 // warps 0-3
    const bool isL1u = (tid >= 256 && tid < 384);   // warps 8-11

    float c = 0.0f, hn_prev = 0.0f;
    if (isL0u) {
        int r = tid >> 6, j = tid & 63;
        sH0[r * 64 + j] = h0g[(size_t)(r0 + r) * Hs + j];
        c = c0g[(size_t)(r0 + r) * Hs + j];
    }
    if (isL1u) {
        int ub = tid - 256, r = ub >> 6, j = ub & 63;
        sH1[r * 64 + j] = h0g[(size_t)Bt * Hs + (size_t)(r0 + r) * Hs + j];
        c = c0g[(size_t)Bt * Hs + (size_t)(r0 + r) * Hs + j];
    }
    float xp0 = 0.f, xp1 = 0.f;
    if (half == 0) {
        xp0 = g_xproj[((size_t)0 * Bt + r0) * GATES + g];
        xp1 = g_xproj[((size_t)0 * Bt + r0 + 1) * GATES + g];
    }
    __syncthreads();

    for (int u = 0; u <= SEQ; u++) {
        // prefetch xproj(u+1)
        float xpn0 = 0.f, xpn1 = 0.f;
        if (half == 0 && u + 1 < SEQ) {
            xpn0 = g_xproj[((size_t)(u + 1) * Bt + r0) * GATES + g];
            xpn1 = g_xproj[((size_t)(u + 1) * Bt + r0 + 1) * GATES + g];
        }

        // deferred head reduce for t=u-2 (hn_prev from iter u-1's L1 update)
        if (isL1u && u >= 2) {
            float p = hn_prev * whj;
#pragma unroll
            for (int off = 16; off; off >>= 1)
                p += __shfl_down_sync(0xffffffffu, p, off);
            if ((tid & 31) == 0) sPr[(u & 1) * 4 + ((tid >> 5) - 8)] = p;
        }

        // ---------- block 1: h0(u-1) feeds Whh0 AND Wih1 ----------
        u64 a0, a1, q0, q1;
        if (half == 0) { a0 = pk(xp0, 0.f); a1 = pk(xp1, 0.f);
                         q0 = pk(b1, 0.f);  q1 = q0; }
        else           { a0 = 0ULL; a1 = 0ULL; q0 = 0ULL; q1 = 0ULL; }
        {
            const ulonglong2* H0 = (const ulonglong2*)sH0;
#pragma unroll
            for (int k = 0; k < 8; k++) {
                ulonglong2 v0 = H0[half * 8 + k];
                ulonglong2 v1 = H0[16 + half * 8 + k];
                a0 = fma2(wh0[2*k],   v0.x, a0);
                a0 = fma2(wh0[2*k+1], v0.y, a0);
                a1 = fma2(wh0[2*k],   v1.x, a1);
                a1 = fma2(wh0[2*k+1], v1.y, a1);
                q0 = fma2(wx1[2*k],   v0.x, q0);
                q0 = fma2(wx1[2*k+1], v0.y, q0);
                q1 = fma2(wx1[2*k],   v1.x, q1);
                q1 = fma2(wx1[2*k+1], v1.y, q1);
            }
        }
        if (u < SEQ) {
            sP[g * 2 + half]       = hsum(a0);
            sP[512 + g * 2 + half] = hsum(a1);
        }
        if (!isL0u) bar_arrive(1);       // release L0 partials; continue

        // ---------- block 2: Whh1 over h1(u-2) ----------
        {
            const ulonglong2* H1 = (const ulonglong2*)sH1;
#pragma unroll
            for (int k = 0; k < 8; k++) {
                ulonglong2 v0 = H1[half * 8 + k];
                ulonglong2 v1 = H1[16 + half * 8 + k];
                q0 = fma2(wh1[2*k],   v0.x, q0);
                q0 = fma2(wh1[2*k+1], v0.y, q0);
                q1 = fma2(wh1[2*k],   v1.x, q1);
                q1 = fma2(wh1[2*k+1], v1.y, q1);
            }
        }
        if (u >= 1) {
            sP[1024 + g * 2 + half] = hsum(q0);
            sP[1536 + g * 2 + half] = hsum(q1);
        }
        xp0 = xpn0; xp1 = xpn1;

        if (isL0u) {
            bar_arrive(2);               // release own L1 partials
            bar_wait(1);                 // wait for everyone's L0 partials
            if (u < SEQ) {               // L0 update, overlapped with block 2
                int r = tid >> 6, j = tid & 63;
                const float2* p = (const float2*)(sP + r * 512);
                float2 vi = p[j], vf = p[64 + j], vg = p[128 + j], vo = p[192 + j];
                float si = sigf(vi.x + vi.y);
                float sf = sigf(vf.x + vf.y);
                float sg = tanha(vg.x + vg.y);
                float so = sigf(vo.x + vo.y);
                c = sf * c + si * sg;
                sH0[r * 64 + j] = so * tanha(c);
            }
        } else if (isL1u) {
            bar_wait(2);                 // wait for everyone's L1 partials
            if (u >= 1) {                // L1 update
                int ub = tid - 256, r = ub >> 6, j = ub & 63;
                const float2* p = (const float2*)(sP + (2 + r) * 512);
                float2 vi = p[j], vf = p[64 + j], vg = p[128 + j], vo = p[192 + j];
                float si = sigf(vi.x + vi.y);
                float sf = sigf(vf.x + vf.y);
                float sg = tanha(vg.x + vg.y);
                float so = sigf(vo.x + vo.y);
                c = sf * c + si * sg;
                float hn = so * tanha(c);
                sH1[r * 64 + j] = hn;
                hn_prev = hn;
            }
            if (u >= 2 && (tid == 256 || tid == 320)) {  // head out, t=u-2
                int row = (tid - 256) >> 6;
                float v = sPr[(u & 1) * 4 + row * 2]
                        + sPr[(u & 1) * 4 + row * 2 + 1] + bh0;
                out[(size_t)(r0 + row) * SEQ + (u - 2)] = sigf(v);
            }
        } else {
            bar_arrive(2);
        }
        __syncthreads();                 // all roles rejoin before next step
    }

    // post-loop: reduce hn_prev (L1 t=SEQ-1) and emit last head sample
    if (isL1u) {
        float p = hn_prev * whj;
#pragma unroll
        for (int off = 16; off; off >>= 1)
            p += __shfl_down_sync(0xffffffffu, p, off);
        if ((tid & 31) == 0) sPr[4 + ((tid >> 5) - 8)] = p;
    }
    __syncthreads();
    if (tid == 384 || tid == 385) {
        int row = tid - 384;
        float v = sPr[4 + row * 2] + sPr[4 + row * 2 + 1] + bh0;
        out[(size_t)(r0 + row) * SEQ + (SEQ - 1)] = sigf(v);
    }

    // final h, c
    const size_t hb = (size_t)Bt * SEQ;
    const size_t cb = hb + 2 * (size_t)Bt * Hs;
    if (isL0u) {
        int r = tid >> 6, j = tid & 63;
        out[hb + (size_t)(r0 + r) * Hs + j] = sH0[r * 64 + j];
        out[cb + (size_t)(r0 + r) * Hs + j] = c;
    }
    if (isL1u) {
        int ub = tid - 256, r = ub >> 6, j = ub & 63;
        out[hb + Bt * Hs + (size_t)(r0 + r) * Hs + j] = sH1[r * 64 + j];
        out[cb + Bt * Hs + (size_t)(r0 + r) * Hs + j] = c;
    }
}

extern "C" void kernel_launch(void* const* d_in, const int* in_sizes, int n_in,
                              void* d_out, int out_size)
{
    const float* x    = (const float*)d_in[0];
    const float* h0   = (const float*)d_in[1];
    const float* c0   = (const float*)d_in[2];
    const float* Wih0 = (const float*)d_in[3];
    const float* Whh0 = (const float*)d_in[4];
    const float* bih0 = (const float*)d_in[5];
    const float* bhh0 = (const float*)d_in[6];
    const float* Wih1 = (const float*)d_in[7];
    const float* Whh1 = (const float*)d_in[8];
    const float* bih1 = (const float*)d_in[9];
    const float* bhh1 = (const float*)d_in[10];
    const float* Wh   = (const float*)d_in[11];
    const float* bh   = (const float*)d_in[12];
    float* out = (float*)d_out;

    dim3 pre_grid(SEQ / 64, Bt);
    xproj_kernel<<<pre_grid, 256>>>(x, Wih0, bih0, bhh0);
    lstm2_r12<<<Bt / 2, 512>>>(h0, c0, Whh0, Wih1, Whh1,
                               bih1, bhh1, Wh, bh, out);
}

// round 13
// speedup vs baseline: 1.1086x; 1.1086x over previous
#include <cuda_runtime.h>
#include <math.h>

#define Hs    64
#define SEQ   2048
#define Bt    256
#define IN    32
#define GATES 256   // 4*H

typedef unsigned long long u64;

// padded by 2 steps so prefetch pointer never runs off the end
__device__ float g_xproj[(size_t)(SEQ + 2) * Bt * GATES];

__device__ __forceinline__ u64 fma2(u64 a, u64 b, u64 c) {
    u64 d;
    asm("fma.rn.f32x2 %0, %1, %2, %3;" : "=l"(d) : "l"(a), "l"(b), "l"(c));
    return d;
}
__device__ __forceinline__ u64 pk(float a, float b) {
    u64 r;
    asm("mov.b64 %0, {%1, %2};" : "=l"(r) : "f"(a), "f"(b));
    return r;
}
__device__ __forceinline__ float hsum(u64 v) {
    float a, b;
    asm("mov.b64 {%0, %1}, %2;" : "=f"(a), "=f"(b) : "l"(v));
    return a + b;
}
__device__ __forceinline__ float ex2a(float x) {
    float y; asm("ex2.approx.f32 %0, %1;" : "=f"(y) : "f"(x)); return y;
}
__device__ __forceinline__ float rcpa(float x) {
    float y; asm("rcp.approx.f32 %0, %1;" : "=f"(y) : "f"(x)); return y;
}
__device__ __forceinline__ float sigf(float x) {
    return rcpa(1.0f + ex2a(-1.4426950408889634f * x));
}
__device__ __forceinline__ float tanha(float x) {
    float y; asm("tanh.approx.f32 %0, %1;" : "=f"(y) : "f"(x)); return y;
}

// ============================================================================
// Prepass (round-4 proven, ~350us): xproj = Wih0·x + bih0 + bhh0
// ============================================================================
__global__ void __launch_bounds__(256)
xproj_kernel(const float* __restrict__ x,
             const float* __restrict__ Wih0,
             const float* __restrict__ bih0,
             const float* __restrict__ bhh0)
{
    __shared__ float sx[64 * IN];
    const int g   = threadIdx.x;
    const int row = blockIdx.y;
    const int t0  = blockIdx.x * 64;

    const float* xs = x + ((size_t)row * SEQ + t0) * IN;
    for (int i = g; i < 64 * IN / 4; i += 256)
        ((float4*)sx)[i] = ((const float4*)xs)[i];

    u64 w[IN / 2];
    const u64* wp = (const u64*)(Wih0 + g * IN);
#pragma unroll
    for (int k = 0; k < IN / 2; k++) w[k] = wp[k];
    const u64 bp = pk(bih0[g] + bhh0[g], 0.0f);
    __syncthreads();

    for (int tt = 0; tt < 64; tt++) {
        const ulonglong2* xv = (const ulonglong2*)(sx + tt * IN);
        u64 a = bp;
#pragma unroll
        for (int k = 0; k < IN / 4; k++) {
            ulonglong2 v = xv[k];
            a = fma2(w[2 * k],     v.x, a);
            a = fma2(w[2 * k + 1], v.y, a);
        }
        g_xproj[((size_t)(t0 + tt) * Bt + row) * GATES + g] = hsum(a);
    }
}

// ============================================================================
// Main: r11 EXACT structure; micro-opts only:
//  - head shfl-reduce moved between a-stores and block2 (latency hidden)
//  - xproj prefetch via incremented pointer
//  - phase-2 index scalars hoisted
// ============================================================================
__global__ void __launch_bounds__(512, 1)
lstm2_r13(const float* __restrict__ h0g,
          const float* __restrict__ c0g,
          const float* __restrict__ Whh0,
          const float* __restrict__ Wih1,
          const float* __restrict__ Whh1,
          const float* __restrict__ bih1,
          const float* __restrict__ bhh1,
          const float* __restrict__ Wh,
          const float* __restrict__ bhp,
          float* __restrict__ out)
{
    __shared__ float sP[4 * 512];    // [layer*2+row][g*2+half]
    __shared__ float sH0[2 * Hs];    // [row][j]
    __shared__ float sH1[2 * Hs];
    __shared__ float sPr[8];         // [parity][4]

    const int tid  = threadIdx.x;
    const int g    = tid & 255;
    const int half = tid >> 8;
    const int r0   = blockIdx.x * 2;

    // register weights: half-rows (32 floats = 16 u64 each)
    u64 wh0[16], wx1[16], wh1[16];
    {
        const u64* p0 = (const u64*)(Whh0 + g * Hs + half * 32);
        const u64* p1 = (const u64*)(Wih1 + g * Hs + half * 32);
        const u64* p2 = (const u64*)(Whh1 + g * Hs + half * 32);
#pragma unroll
        for (int k = 0; k < 16; k++) { wh0[k] = p0[k]; wx1[k] = p1[k]; wh1[k] = p2[k]; }
    }
    const float b1  = bih1[g] + bhh1[g];
    const float bh0 = bhp[0];
    const float whj = Wh[tid & 63];

    const bool isL0u = (tid < 128);
    const bool isL1u = (tid >= 256 && tid < 384);
    // hoisted phase-2 scalars
    const int rr = (tid >> 6) & 1;           // row for updaters
    const int jj = tid & 63;
    const int pbase = (isL0u ? rr : (2 + rr)) * 512;   // sP block offset
    const int hoff  = rr * 64 + jj;

    float c = 0.0f, hn_prev = 0.0f;
    if (isL0u) {
        sH0[hoff] = h0g[(size_t)(r0 + rr) * Hs + jj];
        c = c0g[(size_t)(r0 + rr) * Hs + jj];
    }
    if (isL1u) {
        sH1[hoff] = h0g[(size_t)Bt * Hs + (size_t)(r0 + rr) * Hs + jj];
        c = c0g[(size_t)Bt * Hs + (size_t)(r0 + rr) * Hs + jj];
    }
    // xproj prefetch pointer (half-0 threads only use it)
    const size_t XSTR = (size_t)Bt * GATES;
    const float* xpp = g_xproj + (size_t)r0 * GATES + g;
    float xp0 = 0.f, xp1 = 0.f;
    if (half == 0) { xp0 = xpp[0]; xp1 = xpp[GATES]; }
    xpp += XSTR;
    __syncthreads();

    for (int u = 0; u <= SEQ; u++) {
        // prefetch xproj(u+1) — pointer form, no per-iter IMAD chain
        float xpn0 = 0.f, xpn1 = 0.f;
        if (half == 0) { xpn0 = xpp[0]; xpn1 = xpp[GATES]; }
        xpp += XSTR;

        // ---------- block 1: h0(u-1) feeds Whh0 AND Wih1 ----------
        u64 a0, a1, q0, q1;
        if (half == 0) { a0 = pk(xp0, 0.f); a1 = pk(xp1, 0.f);
                         q0 = pk(b1, 0.f);  q1 = q0; }
        else           { a0 = 0ULL; a1 = 0ULL; q0 = 0ULL; q1 = 0ULL; }
        {
            const ulonglong2* H0 = (const ulonglong2*)sH0;
#pragma unroll
            for (int k = 0; k < 8; k++) {
                ulonglong2 v0 = H0[half * 8 + k];
                ulonglong2 v1 = H0[16 + half * 8 + k];
                a0 = fma2(wh0[2*k],   v0.x, a0);
                a0 = fma2(wh0[2*k+1], v0.y, a0);
                a1 = fma2(wh0[2*k],   v1.x, a1);
                a1 = fma2(wh0[2*k+1], v1.y, a1);
                q0 = fma2(wx1[2*k],   v0.x, q0);
                q0 = fma2(wx1[2*k+1], v0.y, q0);
                q1 = fma2(wx1[2*k],   v1.x, q1);
                q1 = fma2(wx1[2*k+1], v1.y, q1);
            }
        }
        if (u < SEQ) {
            sP[g * 2 + half]       = hsum(a0);
            sP[512 + g * 2 + half] = hsum(a1);
        }

        // deferred head reduce for t=u-2 — SHFL chain overlaps block-2 FMAs
        if (isL1u && u >= 2) {
            float p = hn_prev * whj;
#pragma unroll
            for (int off = 16; off; off >>= 1)
                p += __shfl_down_sync(0xffffffffu, p, off);
            if ((tid & 31) == 0) sPr[(u & 1) * 4 + ((tid >> 5) - 8)] = p;
        }

        // ---------- block 2: Whh1 over h1(u-2) ----------
        {
            const ulonglong2* H1 = (const ulonglong2*)sH1;
#pragma unroll
            for (int k = 0; k < 8; k++) {
                ulonglong2 v0 = H1[half * 8 + k];
                ulonglong2 v1 = H1[16 + half * 8 + k];
                q0 = fma2(wh1[2*k],   v0.x, q0);
                q0 = fma2(wh1[2*k+1], v0.y, q0);
                q1 = fma2(wh1[2*k],   v1.x, q1);
                q1 = fma2(wh1[2*k+1], v1.y, q1);
            }
        }
        if (u >= 1) {
            sP[1024 + g * 2 + half] = hsum(q0);
            sP[1536 + g * 2 + half] = hsum(q1);
        }
        xp0 = xpn0; xp1 = xpn1;
        __syncthreads();

        // ---------- phase 2: combine + activate + update ----------
        if (isL0u && u < SEQ) {                // L0: time u
            const float2* p = (const float2*)(sP + pbase) + jj;
            float2 vi = p[0], vf = p[64], vg = p[128], vo = p[192];
            float si = sigf(vi.x + vi.y);
            float sf = sigf(vf.x + vf.y);
            float sg = tanha(vg.x + vg.y);
            float so = sigf(vo.x + vo.y);
            c = sf * c + si * sg;
            sH0[hoff] = so * tanha(c);
        }
        if (isL1u && u >= 1) {                 // L1: time u-1
            const float2* p = (const float2*)(sP + pbase) + jj;
            float2 vi = p[0], vf = p[64], vg = p[128], vo = p[192];
            float si = sigf(vi.x + vi.y);
            float sf = sigf(vf.x + vf.y);
            float sg = tanha(vg.x + vg.y);
            float so = sigf(vo.x + vo.y);
            c = sf * c + si * sg;
            float hn = so * tanha(c);
            sH1[hoff] = hn;
            hn_prev = hn;
        }
        if (u >= 2 && (tid == 384 || tid == 385)) {  // head out, t=u-2
            int row = tid - 384;
            float v = sPr[(u & 1) * 4 + row * 2]
                    + sPr[(u & 1) * 4 + row * 2 + 1] + bh0;
            out[(size_t)(r0 + row) * SEQ + (u - 2)] = sigf(v);
        }
        __syncthreads();
    }

    // post-loop: reduce hn_prev (L1 t=SEQ-1) and emit last head sample
    if (isL1u) {
        float p = hn_prev * whj;
#pragma unroll
        for (int off = 16; off; off >>= 1)
            p += __shfl_down_sync(0xffffffffu, p, off);
        if ((tid & 31) == 0) sPr[4 + ((tid >> 5) - 8)] = p;
    }
    __syncthreads();
    if (tid == 384 || tid == 385) {
        int row = tid - 384;
        float v = sPr[4 + row * 2] + sPr[4 + row * 2 + 1] + bh0;
        out[(size_t)(r0 + row) * SEQ + (SEQ - 1)] = sigf(v);
    }

    // final h, c
    const size_t hb = (size_t)Bt * SEQ;
    const size_t cb = hb + 2 * (size_t)Bt * Hs;
    if (isL0u) {
        out[hb + (size_t)(r0 + rr) * Hs + jj] = sH0[hoff];
        out[cb + (size_t)(r0 + rr) * Hs + jj] = c;
    }
    if (isL1u) {
        out[hb + Bt * Hs + (size_t)(r0 + rr) * Hs + jj] = sH1[hoff];
        out[cb + Bt * Hs + (size_t)(r0 + rr) * Hs + jj] = c;
    }
}

extern "C" void kernel_launch(void* const* d_in, const int* in_sizes, int n_in,
                              void* d_out, int out_size)
{
    const float* x    = (const float*)d_in[0];
    const float* h0   = (const float*)d_in[1];
    const float* c0   = (const float*)d_in[2];
    const float* Wih0 = (const float*)d_in[3];
    const float* Whh0 = (const float*)d_in[4];
    const float* bih0 = (const float*)d_in[5];
    const float* bhh0 = (const float*)d_in[6];
    const float* Wih1 = (const float*)d_in[7];
    const float* Whh1 = (const float*)d_in[8];
    const float* bih1 = (const float*)d_in[9];
    const float* bhh1 = (const float*)d_in[10];
    const float* Wh   = (const float*)d_in[11];
    const float* bh   = (const float*)d_in[12];
    float* out = (float*)d_out;

    dim3 pre_grid(SEQ / 64, Bt);
    xproj_kernel<<<pre_grid, 256>>>(x, Wih0, bih0, bhh0);
    lstm2_r13<<<Bt / 2, 512>>>(h0, c0, Whh0, Wih1, Whh1,
                               bih1, bhh1, Wh, bh, out);
}

// round 14
// speedup vs baseline: 1.1426x; 1.0307x over previous
#include <cuda_runtime.h>
#include <math.h>

#define Hs    64
#define SEQ   2048
#define Bt    256
#define IN    32
#define GATES 256   // 4*H

typedef unsigned long long u64;

// padded by 2 steps so prefetch pointer never runs off the end
__device__ float g_xproj[(size_t)(SEQ + 2) * Bt * GATES];

__device__ __forceinline__ u64 fma2(u64 a, u64 b, u64 c) {
    u64 d;
    asm("fma.rn.f32x2 %0, %1, %2, %3;" : "=l"(d) : "l"(a), "l"(b), "l"(c));
    return d;
}
__device__ __forceinline__ u64 pk(float a, float b) {
    u64 r;
    asm("mov.b64 %0, {%1, %2};" : "=l"(r) : "f"(a), "f"(b));
    return r;
}
__device__ __forceinline__ float hsum(u64 v) {
    float a, b;
    asm("mov.b64 {%0, %1}, %2;" : "=f"(a), "=f"(b) : "l"(v));
    return a + b;
}
__device__ __forceinline__ float ex2a(float x) {
    float y; asm("ex2.approx.f32 %0, %1;" : "=f"(y) : "f"(x)); return y;
}
__device__ __forceinline__ float rcpa(float x) {
    float y; asm("rcp.approx.f32 %0, %1;" : "=f"(y) : "f"(x)); return y;
}
__device__ __forceinline__ float sigf(float x) {
    return rcpa(1.0f + ex2a(-1.4426950408889634f * x));
}
__device__ __forceinline__ float tanha(float x) {
    float y; asm("tanh.approx.f32 %0, %1;" : "=f"(y) : "f"(x)); return y;
}

// ============================================================================
// Prepass v2: grid (SEQ/256, Bt) = 2048 CTAs; each CTA = 256 timesteps of one
// row. One coalesced 32KB x-chunk load; weights amortized over 256 steps;
// pointer-increment output. (v1 had 8192 CTAs re-loading weights -> 256MB L2.)
// ============================================================================
__global__ void __launch_bounds__(256)
xproj_kernel2(const float* __restrict__ x,
              const float* __restrict__ Wih0,
              const float* __restrict__ bih0,
              const float* __restrict__ bhh0)
{
    __shared__ float sx[256 * IN];   // 32 KB
    const int g   = threadIdx.x;
    const int row = blockIdx.y;
    const int t0  = blockIdx.x * 256;

    // coalesced chunk load: 256 timesteps x 32 floats = 2048 float4
    const float4* xs = (const float4*)(x + ((size_t)row * SEQ + t0) * IN);
#pragma unroll
    for (int i = 0; i < 8; i++)
        ((float4*)sx)[g + i * 256] = xs[g + i * 256];

    u64 w[IN / 2];
    const u64* wp = (const u64*)(Wih0 + g * IN);
#pragma unroll
    for (int k = 0; k < IN / 2; k++) w[k] = wp[k];
    const u64 bp = pk(bih0[g] + bhh0[g], 0.0f);
    __syncthreads();

    float* op = g_xproj + ((size_t)t0 * Bt + row) * GATES + g;
    const size_t OSTR = (size_t)Bt * GATES;
#pragma unroll 2
    for (int tt = 0; tt < 256; tt++) {
        const ulonglong2* xv = (const ulonglong2*)(sx + tt * IN);
        u64 a = bp;
#pragma unroll
        for (int k = 0; k < IN / 4; k++) {
            ulonglong2 v = xv[k];
            a = fma2(w[2 * k],     v.x, a);
            a = fma2(w[2 * k + 1], v.y, a);
        }
        *op = hsum(a);
        op += OSTR;
    }
}

// ============================================================================
// Main: r13 EXACTLY (protected optimum, 2088us).
// ============================================================================
__global__ void __launch_bounds__(512, 1)
lstm2_r13(const float* __restrict__ h0g,
          const float* __restrict__ c0g,
          const float* __restrict__ Whh0,
          const float* __restrict__ Wih1,
          const float* __restrict__ Whh1,
          const float* __restrict__ bih1,
          const float* __restrict__ bhh1,
          const float* __restrict__ Wh,
          const float* __restrict__ bhp,
          float* __restrict__ out)
{
    __shared__ float sP[4 * 512];    // [layer*2+row][g*2+half]
    __shared__ float sH0[2 * Hs];    // [row][j]
    __shared__ float sH1[2 * Hs];
    __shared__ float sPr[8];         // [parity][4]

    const int tid  = threadIdx.x;
    const int g    = tid & 255;
    const int half = tid >> 8;
    const int r0   = blockIdx.x * 2;

    // register weights: half-rows (32 floats = 16 u64 each)
    u64 wh0[16], wx1[16], wh1[16];
    {
        const u64* p0 = (const u64*)(Whh0 + g * Hs + half * 32);
        const u64* p1 = (const u64*)(Wih1 + g * Hs + half * 32);
        const u64* p2 = (const u64*)(Whh1 + g * Hs + half * 32);
#pragma unroll
        for (int k = 0; k < 16; k++) { wh0[k] = p0[k]; wx1[k] = p1[k]; wh1[k] = p2[k]; }
    }
    const float b1  = bih1[g] + bhh1[g];
    const float bh0 = bhp[0];
    const float whj = Wh[tid & 63];

    const bool isL0u = (tid < 128);
    const bool isL1u = (tid >= 256 && tid < 384);
    // hoisted phase-2 scalars
    const int rr = (tid >> 6) & 1;           // row for updaters
    const int jj = tid & 63;
    const int pbase = (isL0u ? rr : (2 + rr)) * 512;   // sP block offset
    const int hoff  = rr * 64 + jj;

    float c = 0.0f, hn_prev = 0.0f;
    if (isL0u) {
        sH0[hoff] = h0g[(size_t)(r0 + rr) * Hs + jj];
        c = c0g[(size_t)(r0 + rr) * Hs + jj];
    }
    if (isL1u) {
        sH1[hoff] = h0g[(size_t)Bt * Hs + (size_t)(r0 + rr) * Hs + jj];
        c = c0g[(size_t)Bt * Hs + (size_t)(r0 + rr) * Hs + jj];
    }
    // xproj prefetch pointer (half-0 threads only use it)
    const size_t XSTR = (size_t)Bt * GATES;
    const float* xpp = g_xproj + (size_t)r0 * GATES + g;
    float xp0 = 0.f, xp1 = 0.f;
    if (half == 0) { xp0 = xpp[0]; xp1 = xpp[GATES]; }
    xpp += XSTR;
    __syncthreads();

    for (int u = 0; u <= SEQ; u++) {
        // prefetch xproj(u+1) — pointer form, no per-iter IMAD chain
        float xpn0 = 0.f, xpn1 = 0.f;
        if (half == 0) { xpn0 = xpp[0]; xpn1 = xpp[GATES]; }
        xpp += XSTR;

        // ---------- block 1: h0(u-1) feeds Whh0 AND Wih1 ----------
        u64 a0, a1, q0, q1;
        if (half == 0) { a0 = pk(xp0, 0.f); a1 = pk(xp1, 0.f);
                         q0 = pk(b1, 0.f);  q1 = q0; }
        else           { a0 = 0ULL; a1 = 0ULL; q0 = 0ULL; q1 = 0ULL; }
        {
            const ulonglong2* H0 = (const ulonglong2*)sH0;
#pragma unroll
            for (int k = 0; k < 8; k++) {
                ulonglong2 v0 = H0[half * 8 + k];
                ulonglong2 v1 = H0[16 + half * 8 + k];
                a0 = fma2(wh0[2*k],   v0.x, a0);
                a0 = fma2(wh0[2*k+1], v0.y, a0);
                a1 = fma2(wh0[2*k],   v1.x, a1);
                a1 = fma2(wh0[2*k+1], v1.y, a1);
                q0 = fma2(wx1[2*k],   v0.x, q0);
                q0 = fma2(wx1[2*k+1], v0.y, q0);
                q1 = fma2(wx1[2*k],   v1.x, q1);
                q1 = fma2(wx1[2*k+1], v1.y, q1);
            }
        }
        if (u < SEQ) {
            sP[g * 2 + half]       = hsum(a0);
            sP[512 + g * 2 + half] = hsum(a1);
        }

        // deferred head reduce for t=u-2 — SHFL chain overlaps block-2 FMAs
        if (isL1u && u >= 2) {
            float p = hn_prev * whj;
#pragma unroll
            for (int off = 16; off; off >>= 1)
                p += __shfl_down_sync(0xffffffffu, p, off);
            if ((tid & 31) == 0) sPr[(u & 1) * 4 + ((tid >> 5) - 8)] = p;
        }

        // ---------- block 2: Whh1 over h1(u-2) ----------
        {
            const ulonglong2* H1 = (const ulonglong2*)sH1;
#pragma unroll
            for (int k = 0; k < 8; k++) {
                ulonglong2 v0 = H1[half * 8 + k];
                ulonglong2 v1 = H1[16 + half * 8 + k];
                q0 = fma2(wh1[2*k],   v0.x, q0);
                q0 = fma2(wh1[2*k+1], v0.y, q0);
                q1 = fma2(wh1[2*k],   v1.x, q1);
                q1 = fma2(wh1[2*k+1], v1.y, q1);
            }
        }
        if (u >= 1) {
            sP[1024 + g * 2 + half] = hsum(q0);
            sP[1536 + g * 2 + half] = hsum(q1);
        }
        xp0 = xpn0; xp1 = xpn1;
        __syncthreads();

        // ---------- phase 2: combine + activate + update ----------
        if (isL0u && u < SEQ) {                // L0: time u
            const float2* p = (const float2*)(sP + pbase) + jj;
            float2 vi = p[0], vf = p[64], vg = p[128], vo = p[192];
            float si = sigf(vi.x + vi.y);
            float sf = sigf(vf.x + vf.y);
            float sg = tanha(vg.x + vg.y);
            float so = sigf(vo.x + vo.y);
            c = sf * c + si * sg;
            sH0[hoff] = so * tanha(c);
        }
        if (isL1u && u >= 1) {                 // L1: time u-1
            const float2* p = (const float2*)(sP + pbase) + jj;
            float2 vi = p[0], vf = p[64], vg = p[128], vo = p[192];
            float si = sigf(vi.x + vi.y);
            float sf = sigf(vf.x + vf.y);
            float sg = tanha(vg.x + vg.y);
            float so = sigf(vo.x + vo.y);
            c = sf * c + si * sg;
            float hn = so * tanha(c);
            sH1[hoff] = hn;
            hn_prev = hn;
        }
        if (u >= 2 && (tid == 384 || tid == 385)) {  // head out, t=u-2
            int row = tid - 384;
            float v = sPr[(u & 1) * 4 + row * 2]
                    + sPr[(u & 1) * 4 + row * 2 + 1] + bh0;
            out[(size_t)(r0 + row) * SEQ + (u - 2)] = sigf(v);
        }
        __syncthreads();
    }

    // post-loop: reduce hn_prev (L1 t=SEQ-1) and emit last head sample
    if (isL1u) {
        float p = hn_prev * whj;
#pragma unroll
        for (int off = 16; off; off >>= 1)
            p += __shfl_down_sync(0xffffffffu, p, off);
        if ((tid & 31) == 0) sPr[4 + ((tid >> 5) - 8)] = p;
    }
    __syncthreads();
    if (tid == 384 || tid == 385) {
        int row = tid - 384;
        float v = sPr[4 + row * 2] + sPr[4 + row * 2 + 1] + bh0;
        out[(size_t)(r0 + row) * SEQ + (SEQ - 1)] = sigf(v);
    }

    // final h, c
    const size_t hb = (size_t)Bt * SEQ;
    const size_t cb = hb + 2 * (size_t)Bt * Hs;
    if (isL0u) {
        out[hb + (size_t)(r0 + rr) * Hs + jj] = sH0[hoff];
        out[cb + (size_t)(r0 + rr) * Hs + jj] = c;
    }
    if (isL1u) {
        out[hb + Bt * Hs + (size_t)(r0 + rr) * Hs + jj] = sH1[hoff];
        out[cb + Bt * Hs + (size_t)(r0 + rr) * Hs + jj] = c;
    }
}

extern "C" void kernel_launch(void* const* d_in, const int* in_sizes, int n_in,
                              void* d_out, int out_size)
{
    const float* x    = (const float*)d_in[0];
    const float* h0   = (const float*)d_in[1];
    const float* c0   = (const float*)d_in[2];
    const float* Wih0 = (const float*)d_in[3];
    const float* Whh0 = (const float*)d_in[4];
    const float* bih0 = (const float*)d_in[5];
    const float* bhh0 = (const float*)d_in[6];
    const float* Wih1 = (const float*)d_in[7];
    const float* Whh1 = (const float*)d_in[8];
    const float* bih1 = (const float*)d_in[9];
    const float* bhh1 = (const float*)d_in[10];
    const float* Wh   = (const float*)d_in[11];
    const float* bh   = (const float*)d_in[12];
    float* out = (float*)d_out;

    dim3 pre_grid(SEQ / 256, Bt);
    xproj_kernel2<<<pre_grid, 256>>>(x, Wih0, bih0, bhh0);
    lstm2_r13<<<Bt / 2, 512>>>(h0, c0, Whh0, Wih1, Whh1,
                               bih1, bhh1, Wh, bh, out);
}

// round 15
// speedup vs baseline: 1.1814x; 1.0339x over previous
#include <cuda_runtime.h>
#include <math.h>

#define Hs    64
#define SEQ   2048
#define Bt    256
#define IN    32
#define GATES 256   // 4*H

typedef unsigned long long u64;

// padded by 2 steps so prefetch pointer never runs off the end
__device__ float g_xproj[(size_t)(SEQ + 2) * Bt * GATES];

__device__ __forceinline__ u64 fma2(u64 a, u64 b, u64 c) {
    u64 d;
    asm("fma.rn.f32x2 %0, %1, %2, %3;" : "=l"(d) : "l"(a), "l"(b), "l"(c));
    return d;
}
__device__ __forceinline__ u64 pk(float a, float b) {
    u64 r;
    asm("mov.b64 %0, {%1, %2};" : "=l"(r) : "f"(a), "f"(b));
    return r;
}
__device__ __forceinline__ float hsum(u64 v) {
    float a, b;
    asm("mov.b64 {%0, %1}, %2;" : "=f"(a), "=f"(b) : "l"(v));
    return a + b;
}
__device__ __forceinline__ float ex2a(float x) {
    float y; asm("ex2.approx.f32 %0, %1;" : "=f"(y) : "f"(x)); return y;
}
__device__ __forceinline__ float rcpa(float x) {
    float y; asm("rcp.approx.f32 %0, %1;" : "=f"(y) : "f"(x)); return y;
}
// exact-path sigmoid (head output only)
__device__ __forceinline__ float sigf(float x) {
    return rcpa(1.0f + ex2a(-1.4426950408889634f * x));
}
__device__ __forceinline__ float tanha(float x) {
    float y; asm("tanh.approx.f32 %0, %1;" : "=f"(y) : "f"(x)); return y;
}
// fast sigmoid via MUFU.TANH: 1 MUFU, 24-cyc chain
__device__ __forceinline__ float sigt(float x) {
    return fmaf(0.5f, tanha(0.5f * x), 0.5f);
}

// ============================================================================
// Prepass v3: grid (SEQ/256, Bt), 512 threads = (gate, t-parity).
// 128 serial iterations/thread; 2 CTAs/SM resident -> latency covered.
// ============================================================================
__global__ void __launch_bounds__(512)
xproj_kernel3(const float* __restrict__ x,
              const float* __restrict__ Wih0,
              const float* __restrict__ bih0,
              const float* __restrict__ bhh0)
{
    __shared__ float sx[256 * IN];   // 32 KB
    const int tid  = threadIdx.x;
    const int g    = tid & 255;
    const int tpar = tid >> 8;       // time parity 0/1
    const int row  = blockIdx.y;
    const int t0   = blockIdx.x * 256;

    // coalesced chunk load: 256 timesteps x 32 floats = 2048 float4
    const float4* xs = (const float4*)(x + ((size_t)row * SEQ + t0) * IN);
#pragma unroll
    for (int i = 0; i < 4; i++)
        ((float4*)sx)[tid + i * 512] = xs[tid + i * 512];

    u64 w[IN / 2];
    const u64* wp = (const u64*)(Wih0 + g * IN);
#pragma unroll
    for (int k = 0; k < IN / 2; k++) w[k] = wp[k];
    const u64 bp = pk(bih0[g] + bhh0[g], 0.0f);
    __syncthreads();

    float* op = g_xproj + (((size_t)t0 + tpar) * Bt + row) * GATES + g;
    const size_t OSTR = 2 * (size_t)Bt * GATES;
#pragma unroll 2
    for (int tt = tpar; tt < 256; tt += 2) {
        const ulonglong2* xv = (const ulonglong2*)(sx + tt * IN);
        u64 a = bp;
#pragma unroll
        for (int k = 0; k < IN / 4; k++) {
            ulonglong2 v = xv[k];
            a = fma2(w[2 * k],     v.x, a);
            a = fma2(w[2 * k + 1], v.y, a);
        }
        *op = hsum(a);
        op += OSTR;
    }
}

// ============================================================================
// Main: r13 structure EXACTLY; phase-2 sigmoids -> sigt (MUFU.TANH based).
// ============================================================================
__global__ void __launch_bounds__(512, 1)
lstm2_r15(const float* __restrict__ h0g,
          const float* __restrict__ c0g,
          const float* __restrict__ Whh0,
          const float* __restrict__ Wih1,
          const float* __restrict__ Whh1,
          const float* __restrict__ bih1,
          const float* __restrict__ bhh1,
          const float* __restrict__ Wh,
          const float* __restrict__ bhp,
          float* __restrict__ out)
{
    __shared__ float sP[4 * 512];    // [layer*2+row][g*2+half]
    __shared__ float sH0[2 * Hs];    // [row][j]
    __shared__ float sH1[2 * Hs];
    __shared__ float sPr[8];         // [parity][4]

    const int tid  = threadIdx.x;
    const int g    = tid & 255;
    const int half = tid >> 8;
    const int r0   = blockIdx.x * 2;

    // register weights: half-rows (32 floats = 16 u64 each)
    u64 wh0[16], wx1[16], wh1[16];
    {
        const u64* p0 = (const u64*)(Whh0 + g * Hs + half * 32);
        const u64* p1 = (const u64*)(Wih1 + g * Hs + half * 32);
        const u64* p2 = (const u64*)(Whh1 + g * Hs + half * 32);
#pragma unroll
        for (int k = 0; k < 16; k++) { wh0[k] = p0[k]; wx1[k] = p1[k]; wh1[k] = p2[k]; }
    }
    const float b1  = bih1[g] + bhh1[g];
    const float bh0 = bhp[0];
    const float whj = Wh[tid & 63];

    const bool isL0u = (tid < 128);
    const bool isL1u = (tid >= 256 && tid < 384);
    // hoisted phase-2 scalars
    const int rr = (tid >> 6) & 1;           // row for updaters
    const int jj = tid & 63;
    const int pbase = (isL0u ? rr : (2 + rr)) * 512;   // sP block offset
    const int hoff  = rr * 64 + jj;

    float c = 0.0f, hn_prev = 0.0f;
    if (isL0u) {
        sH0[hoff] = h0g[(size_t)(r0 + rr) * Hs + jj];
        c = c0g[(size_t)(r0 + rr) * Hs + jj];
    }
    if (isL1u) {
        sH1[hoff] = h0g[(size_t)Bt * Hs + (size_t)(r0 + rr) * Hs + jj];
        c = c0g[(size_t)Bt * Hs + (size_t)(r0 + rr) * Hs + jj];
    }
    // xproj prefetch pointer (half-0 threads only use it)
    const size_t XSTR = (size_t)Bt * GATES;
    const float* xpp = g_xproj + (size_t)r0 * GATES + g;
    float xp0 = 0.f, xp1 = 0.f;
    if (half == 0) { xp0 = xpp[0]; xp1 = xpp[GATES]; }
    xpp += XSTR;
    __syncthreads();

    for (int u = 0; u <= SEQ; u++) {
        // prefetch xproj(u+1) — pointer form, no per-iter IMAD chain
        float xpn0 = 0.f, xpn1 = 0.f;
        if (half == 0) { xpn0 = xpp[0]; xpn1 = xpp[GATES]; }
        xpp += XSTR;

        // ---------- block 1: h0(u-1) feeds Whh0 AND Wih1 ----------
        u64 a0, a1, q0, q1;
        if (half == 0) { a0 = pk(xp0, 0.f); a1 = pk(xp1, 0.f);
                         q0 = pk(b1, 0.f);  q1 = q0; }
        else           { a0 = 0ULL; a1 = 0ULL; q0 = 0ULL; q1 = 0ULL; }
        {
            const ulonglong2* H0 = (const ulonglong2*)sH0;
#pragma unroll
            for (int k = 0; k < 8; k++) {
                ulonglong2 v0 = H0[half * 8 + k];
                ulonglong2 v1 = H0[16 + half * 8 + k];
                a0 = fma2(wh0[2*k],   v0.x, a0);
                a0 = fma2(wh0[2*k+1], v0.y, a0);
                a1 = fma2(wh0[2*k],   v1.x, a1);
                a1 = fma2(wh0[2*k+1], v1.y, a1);
                q0 = fma2(wx1[2*k],   v0.x, q0);
                q0 = fma2(wx1[2*k+1], v0.y, q0);
                q1 = fma2(wx1[2*k],   v1.x, q1);
                q1 = fma2(wx1[2*k+1], v1.y, q1);
            }
        }
        if (u < SEQ) {
            sP[g * 2 + half]       = hsum(a0);
            sP[512 + g * 2 + half] = hsum(a1);
        }

        // deferred head reduce for t=u-2 — SHFL chain overlaps block-2 FMAs
        if (isL1u && u >= 2) {
            float p = hn_prev * whj;
#pragma unroll
            for (int off = 16; off; off >>= 1)
                p += __shfl_down_sync(0xffffffffu, p, off);
            if ((tid & 31) == 0) sPr[(u & 1) * 4 + ((tid >> 5) - 8)] = p;
        }

        // ---------- block 2: Whh1 over h1(u-2) ----------
        {
            const ulonglong2* H1 = (const ulonglong2*)sH1;
#pragma unroll
            for (int k = 0; k < 8; k++) {
                ulonglong2 v0 = H1[half * 8 + k];
                ulonglong2 v1 = H1[16 + half * 8 + k];
                q0 = fma2(wh1[2*k],   v0.x, q0);
                q0 = fma2(wh1[2*k+1], v0.y, q0);
                q1 = fma2(wh1[2*k],   v1.x, q1);
                q1 = fma2(wh1[2*k+1], v1.y, q1);
            }
        }
        if (u >= 1) {
            sP[1024 + g * 2 + half] = hsum(q0);
            sP[1536 + g * 2 + half] = hsum(q1);
        }
        xp0 = xpn0; xp1 = xpn1;
        __syncthreads();

        // ---------- phase 2: combine + activate + update ----------
        if (isL0u && u < SEQ) {                // L0: time u
            const float2* p = (const float2*)(sP + pbase) + jj;
            float2 vi = p[0], vf = p[64], vg = p[128], vo = p[192];
            float si = sigt(vi.x + vi.y);
            float sf = sigt(vf.x + vf.y);
            float sg = tanha(vg.x + vg.y);
            float so = sigt(vo.x + vo.y);
            c = sf * c + si * sg;
            sH0[hoff] = so * tanha(c);
        }
        if (isL1u && u >= 1) {                 // L1: time u-1
            const float2* p = (const float2*)(sP + pbase) + jj;
            float2 vi = p[0], vf = p[64], vg = p[128], vo = p[192];
            float si = sigt(vi.x + vi.y);
            float sf = sigt(vf.x + vf.y);
            float sg = tanha(vg.x + vg.y);
            float so = sigt(vo.x + vo.y);
            c = sf * c + si * sg;
            float hn = so * tanha(c);
            sH1[hoff] = hn;
            hn_prev = hn;
        }
        if (u >= 2 && (tid == 384 || tid == 385)) {  // head out, t=u-2
            int row = tid - 384;
            float v = sPr[(u & 1) * 4 + row * 2]
                    + sPr[(u & 1) * 4 + row * 2 + 1] + bh0;
            out[(size_t)(r0 + row) * SEQ + (u - 2)] = sigf(v);
        }
        __syncthreads();
    }

    // post-loop: reduce hn_prev (L1 t=SEQ-1) and emit last head sample
    if (isL1u) {
        float p = hn_prev * whj;
#pragma unroll
        for (int off = 16; off; off >>= 1)
            p += __shfl_down_sync(0xffffffffu, p, off);
        if ((tid & 31) == 0) sPr[4 + ((tid >> 5) - 8)] = p;
    }
    __syncthreads();
    if (tid == 384 || tid == 385) {
        int row = tid - 384;
        float v = sPr[4 + row * 2] + sPr[4 + row * 2 + 1] + bh0;
        out[(size_t)(r0 + row) * SEQ + (SEQ - 1)] = sigf(v);
    }

    // final h, c
    const size_t hb = (size_t)Bt * SEQ;
    const size_t cb = hb + 2 * (size_t)Bt * Hs;
    if (isL0u) {
        out[hb + (size_t)(r0 + rr) * Hs + jj] = sH0[hoff];
        out[cb + (size_t)(r0 + rr) * Hs + jj] = c;
    }
    if (isL1u) {
        out[hb + Bt * Hs + (size_t)(r0 + rr) * Hs + jj] = sH1[hoff];
        out[cb + Bt * Hs + (size_t)(r0 + rr) * Hs + jj] = c;
    }
}

extern "C" void kernel_launch(void* const* d_in, const int* in_sizes, int n_in,
                              void* d_out, int out_size)
{
    const float* x    = (const float*)d_in[0];
    const float* h0   = (const float*)d_in[1];
    const float* c0   = (const float*)d_in[2];
    const float* Wih0 = (const float*)d_in[3];
    const float* Whh0 = (const float*)d_in[4];
    const float* bih0 = (const float*)d_in[5];
    const float* bhh0 = (const float*)d_in[6];
    const float* Wih1 = (const float*)d_in[7];
    const float* Whh1 = (const float*)d_in[8];
    const float* bih1 = (const float*)d_in[9];
    const float* bhh1 = (const float*)d_in[10];
    const float* Wh   = (const float*)d_in[11];
    const float* bh   = (const float*)d_in[12];
    float* out = (float*)d_out;

    dim3 pre_grid(SEQ / 256, Bt);
    xproj_kernel3<<<pre_grid, 512>>>(x, Wih0, bih0, bhh0);
    lstm2_r15<<<Bt / 2, 512>>>(h0, c0, Whh0, Wih1, Whh1,
                               bih1, bhh1, Wh, bh, out);
}